// round 12
// baseline (speedup 1.0000x reference)
#include <cuda_runtime.h>

// LSTM seq2seq: B=64, T=512, F=64, H=512, FUT=96 — persistent v6.
// R10/R11 ncu: LDS data-path bound (L1 64% vs fma 24%). Fix: amortize weight
// bytes over 8 rows per lane. K split across 8 warps (k2 = w mod 8), transposed
// activation staging buf[k2][row], cross-warp smem reduction + per-thread finalize.
// 3 B smem per FFMA2 (was 6); dual phase 2 B.

#define BB 64
#define TT 512
#define FF 64
#define HH 512
#define FUT 96
#define BH (BB*HH)          // 32768

#define NBLK 128
#define NTHR 256
#define WSS   514           // ulonglong2 per j row (K=512): 257 k2-pairs padded
#define WSS64 66            // ulonglong2 per j row (K=64)
#define ACT_U64 2112        // one act buffer: 32 k2 x 66 (u64, transposed)
#define RED_F4  2304        // reduction tile: 8 warps x 32 lanes x 9 float4

typedef unsigned long long u64;

// ---------------- device scratch ----------------
__device__ float  g_y0[TT*BB*HH];
__device__ float  g_h1hist[FUT*BB*HH];
__device__ float  g_zero[BH];
__device__ float  g_c0[BH], g_c1[BH];
__device__ float  g_h1A[BH], g_h1B[BH], g_h0A[BH], g_h0B[BH];

// pair-packed weights: per (j,k2): float4 {i(k),i(k+1),f(k),f(k+1)}, float4 {g..,o..}
__device__ float4 g_pW_enc_ih0[HH*FF];
__device__ float4 g_pW_enc_hh0[HH*HH];
__device__ float4 g_pW_enc_ih1[HH*HH];
__device__ float4 g_pW_enc_hh1[HH*HH];
__device__ float4 g_pW_dec_ih0[HH*FF];
__device__ float4 g_pW_dec_hh0[HH*HH];
__device__ float4 g_pW_dec_ih1[HH*HH];
__device__ float4 g_pW_dec_hh1[HH*HH];
__device__ float4 g_pW_dec0c[HH*HH];
__device__ float4 g_pb_enc0[HH], g_pb_enc1[HH], g_pb_dec0[HH], g_pb_dec1[HH], g_pb_dec0c[HH];

__device__ unsigned g_bgen;
__device__ unsigned g_flag[NBLK*8];

// ---------------- f32x2 helpers ----------------
__device__ __forceinline__ u64 pack2(float a, float b) {
    u64 r;
    asm("mov.b64 %0, {%1, %2};" : "=l"(r) : "r"(__float_as_uint(a)), "r"(__float_as_uint(b)));
    return r;
}
__device__ __forceinline__ float2 unpack2(u64 v) {
    unsigned int lo, hi;
    asm("mov.b64 {%0, %1}, %2;" : "=r"(lo), "=r"(hi) : "l"(v));
    return make_float2(__uint_as_float(lo), __uint_as_float(hi));
}
__device__ __forceinline__ void ffma2(u64& d, u64 a, u64 b) {
    asm("fma.rn.f32x2 %0, %1, %2, %0;" : "+l"(d) : "l"(a), "l"(b));
}

// ---------------- flag-tree grid barrier ----------------
__device__ __forceinline__ void grid_barrier(unsigned gen) {
    __syncthreads();
    int tid = threadIdx.x;
    if (blockIdx.x == 0) {
        if (tid > 0 && tid < NBLK) {
            unsigned v;
            do {
                asm volatile("ld.acquire.gpu.u32 %0, [%1];" : "=r"(v) : "l"(&g_flag[tid * 8]));
            } while (v < gen);
        }
        __syncthreads();
        if (tid == 0) {
            asm volatile("st.release.gpu.u32 [%0], %1;" :: "l"(&g_bgen), "r"(gen));
        }
    } else {
        if (tid == 0) {
            asm volatile("st.release.gpu.u32 [%0], %1;" :: "l"(&g_flag[blockIdx.x * 8]), "r"(gen));
            unsigned v;
            do {
                asm volatile("ld.acquire.gpu.u32 %0, [%1];" : "=r"(v) : "l"(&g_bgen));
            } while (v < gen);
        }
        __syncthreads();
    }
}

// ---------------- chunk compute: lane = (jl, rg), 8 rows per lane ----------------
// A[u*4+g]: row rg*8+u, gates g in {i,f,g,o}; each u64 = 2 k-lane partials.
// Warp w covers k2l = w + 8*kk, kk 0..3 within a 32-k2 chunk.
__device__ __forceinline__ void chunk_s(
    u64* __restrict__ A, const ulonglong2* __restrict__ Wt,
    const u64* __restrict__ ab, int w, int rg)
{
#pragma unroll
    for (int kk = 0; kk < 4; kk++) {
        int k2l = w + 8 * kk;
        const u64* ar = ab + k2l * 66 + rg * 8;
        ulonglong2 a0 = *(const ulonglong2*)(ar);
        ulonglong2 a1 = *(const ulonglong2*)(ar + 2);
        ulonglong2 a2 = *(const ulonglong2*)(ar + 4);
        ulonglong2 a3 = *(const ulonglong2*)(ar + 6);
        ulonglong2 wif = Wt[k2l * 2], wgo = Wt[k2l * 2 + 1];
        u64 au[8] = {a0.x, a0.y, a1.x, a1.y, a2.x, a2.y, a3.x, a3.y};
#pragma unroll
        for (int u = 0; u < 8; u++) {
            ffma2(A[u * 4 + 0], au[u], wif.x);
            ffma2(A[u * 4 + 1], au[u], wif.y);
            ffma2(A[u * 4 + 2], au[u], wgo.x);
            ffma2(A[u * 4 + 3], au[u], wgo.y);
        }
    }
}

__device__ __forceinline__ void chunk_d(
    u64* __restrict__ A, u64* __restrict__ B,
    const ulonglong2* __restrict__ Wa, const ulonglong2* __restrict__ Wb,
    const u64* __restrict__ ab, int w, int rg)
{
#pragma unroll
    for (int kk = 0; kk < 4; kk++) {
        int k2l = w + 8 * kk;
        const u64* ar = ab + k2l * 66 + rg * 8;
        ulonglong2 a0 = *(const ulonglong2*)(ar);
        ulonglong2 a1 = *(const ulonglong2*)(ar + 2);
        ulonglong2 a2 = *(const ulonglong2*)(ar + 4);
        ulonglong2 a3 = *(const ulonglong2*)(ar + 6);
        ulonglong2 waif = Wa[k2l * 2], wago = Wa[k2l * 2 + 1];
        ulonglong2 wbif = Wb[k2l * 2], wbgo = Wb[k2l * 2 + 1];
        u64 au[8] = {a0.x, a0.y, a1.x, a1.y, a2.x, a2.y, a3.x, a3.y};
#pragma unroll
        for (int u = 0; u < 8; u++) {
            ffma2(A[u * 4 + 0], au[u], waif.x);
            ffma2(A[u * 4 + 1], au[u], waif.y);
            ffma2(A[u * 4 + 2], au[u], wago.x);
            ffma2(A[u * 4 + 3], au[u], wago.y);
            ffma2(B[u * 4 + 0], au[u], wbif.x);
            ffma2(B[u * 4 + 1], au[u], wbif.y);
            ffma2(B[u * 4 + 2], au[u], wbgo.x);
            ffma2(B[u * 4 + 3], au[u], wbgo.y);
        }
    }
}

// ---------------- staged K=512 phase; x: [64][xs4 float4] row-major ----------------
template <bool DUAL>
__device__ __forceinline__ void phase512(
    u64* __restrict__ A, u64* __restrict__ B,
    const float* __restrict__ x, int xs4,
    const ulonglong2* __restrict__ Wa, const ulonglong2* __restrict__ Wb,
    u64* __restrict__ act, int tid, int w, int jl, int rg)
{
    const float4* x4 = (const float4*)x;
    int r = tid & 63, qg = tid >> 6;             // 256 thr: 4 stagers per row
    const float4* xr = x4 + (size_t)r * xs4 + qg * 4;
    float4 pf[4];
#pragma unroll
    for (int u = 0; u < 4; u++) pf[u] = xr[u];
#pragma unroll 1
    for (int c = 0; c < 8; c++) {
        u64* buf = act + (c & 1) * ACT_U64;
#pragma unroll
        for (int u = 0; u < 4; u++) {
            int q = qg * 4 + u;
            buf[(2 * q) * 66 + r]     = pack2(pf[u].x, pf[u].y);
            buf[(2 * q + 1) * 66 + r] = pack2(pf[u].z, pf[u].w);
        }
        __syncthreads();
        if (c < 7) {
#pragma unroll
            for (int u = 0; u < 4; u++) pf[u] = xr[(c + 1) * 16 + u];
        }
        if (DUAL) chunk_d(A, B, Wa + jl * WSS + c * 64, Wb + jl * WSS + c * 64, buf, w, rg);
        else      chunk_s(A, Wa + jl * WSS + c * 64, buf, w, rg);
    }
}

// K=64 phase (input projection); uses act buffer 1 (parity-safe vs phase512 start).
__device__ __forceinline__ void phase64_s(
    u64* __restrict__ A, const float* __restrict__ x, int xs4,
    const ulonglong2* __restrict__ W, u64* __restrict__ act,
    int tid, int w, int jl, int rg)
{
    const float4* x4 = (const float4*)x;
    int r = tid & 63, qg = tid >> 6;
    const float4* xr = x4 + (size_t)r * xs4 + qg * 4;
    u64* buf = act + ACT_U64;
#pragma unroll
    for (int u = 0; u < 4; u++) {
        float4 v = xr[u];
        int q = qg * 4 + u;
        buf[(2 * q) * 66 + r]     = pack2(v.x, v.y);
        buf[(2 * q + 1) * 66 + r] = pack2(v.z, v.w);
    }
    __syncthreads();
    chunk_s(A, W + jl * WSS64, buf, w, rg);
}

// ---------------- reduction: fold k-lanes, store float4 per (lane,row) ----------------
__device__ __forceinline__ void red_store(const u64* __restrict__ A,
                                          float4* __restrict__ red4, int w, int l)
{
    float4* p = red4 + (w * 32 + l) * 9;
#pragma unroll
    for (int u = 0; u < 8; u++) {
        float2 a = unpack2(A[u * 4 + 0]), b = unpack2(A[u * 4 + 1]);
        float2 cc = unpack2(A[u * 4 + 2]), d = unpack2(A[u * 4 + 3]);
        p[u] = make_float4(a.x + a.y, b.x + b.y, cc.x + cc.y, d.x + d.y);
    }
}

// Finalize one cell (after __syncthreads): sum 8 warp partials + bias, LSTM math.
__device__ __forceinline__ float fin_cell(const float4* __restrict__ red4,
                                          int cell, float4 bias, float& c)
{
    int r = cell >> 2, jl2 = cell & 3;
    int off = ((r >> 3) * 4 + jl2) * 9 + (r & 7);
    float4 s = bias;
#pragma unroll
    for (int w2 = 0; w2 < 8; w2++) {
        float4 v = red4[w2 * 288 + off];
        s.x += v.x; s.y += v.y; s.z += v.z; s.w += v.w;
    }
    float si = 1.f / (1.f + __expf(-s.x));
    float sf = 1.f / (1.f + __expf(-s.y));
    float so = 1.f / (1.f + __expf(-s.w));
    float cn = sf * c + si * tanhf(s.z);
    c = cn;
    return so * tanhf(cn);
}

__device__ __forceinline__ void zero_acc(u64* A) {
#pragma unroll
    for (int i = 0; i < 32; i++) A[i] = 0ULL;
}

#define ENC_SMEM ((3*4*WSS + 4*WSS64)*16 + 2*ACT_U64*8 + RED_F4*16)   // 173568
#define DEC_SMEM ((4*4*WSS + 4*WSS64)*16 + 2*ACT_U64*8 + RED_F4*16)   // 206464

// ---------------- persistent encoder: L0 + L1 software-pipelined ----------------
__global__ void __launch_bounds__(NTHR, 1) enc_kernel(
    const float* __restrict__ in_seq,
    const float4* __restrict__ pW0x, const float4* __restrict__ pW0h,
    const float4* __restrict__ pW1x, const float4* __restrict__ pW1h,
    const float4* __restrict__ pb0, const float4* __restrict__ pb1,
    const float* __restrict__ zerobuf,
    float* __restrict__ y0, float* __restrict__ h1A, float* __restrict__ h1B,
    float* __restrict__ c0out, float* __restrict__ c1out)
{
    extern __shared__ __align__(16) unsigned char smraw[];
    ulonglong2* W0h = (ulonglong2*)smraw;
    ulonglong2* W1x = W0h + 4 * WSS;
    ulonglong2* W1h = W1x + 4 * WSS;
    ulonglong2* W0x = W1h + 4 * WSS;
    u64* act = (u64*)(W0x + 4 * WSS64);
    float4* red4 = (float4*)(act + 2 * ACT_U64);

    int tid = threadIdx.x;
    int w = tid >> 5, l = tid & 31, jl = l & 3, rg = l >> 2;
    int j0 = blockIdx.x * 4;
    // finalizer mapping: 1 cell per thread
    int cell = tid;
    int fr = cell >> 2, fjl = cell & 3;
    int fidx = (fr << 9) + j0 + fjl;

    {   // load smem weight tiles (once)
        const ulonglong2* g0h = (const ulonglong2*)pW0h + (size_t)j0 * HH;
        const ulonglong2* g1x = (const ulonglong2*)pW1x + (size_t)j0 * HH;
        const ulonglong2* g1h = (const ulonglong2*)pW1h + (size_t)j0 * HH;
#pragma unroll 2
        for (int i = tid; i < 4 * HH; i += NTHR) {
            int jj = i >> 9, kk = i & 511;
            W0h[jj * WSS + kk] = g0h[i];
            W1x[jj * WSS + kk] = g1x[i];
            W1h[jj * WSS + kk] = g1h[i];
        }
        const ulonglong2* g0x = (const ulonglong2*)pW0x + (size_t)j0 * FF;
        if (tid < 4 * FF) {
            int jj = tid >> 6, kk = tid & 63;
            W0x[jj * WSS64 + kk] = g0x[tid];
        }
    }
    float4 bE0 = pb0[j0 + fjl], bE1 = pb1[j0 + fjl];
    float c0 = 0.f, c1 = 0.f;
    __syncthreads();

    unsigned gen = 0;
    for (int slot = 0; slot <= TT; slot++) {
        bool doL0 = (slot < TT);
        bool doL1 = (slot > 0);
        const float* yprev = (slot == 0) ? zerobuf : (y0 + (size_t)(slot - 1) * BH);

        u64 A[32], B[32];
        if (doL0) {
            zero_acc(A);
            phase64_s(A, in_seq + (size_t)slot * FF, TT * FF / 4, W0x, act, tid, w, jl, rg);
        }
        if (doL1) zero_acc(B);

        if (doL0 && doL1)
            phase512<true>(A, B, yprev, 128, W0h, W1x, act, tid, w, jl, rg);
        else if (doL0)
            phase512<false>(A, A, yprev, 128, W0h, W0h, act, tid, w, jl, rg);
        else
            phase512<false>(B, B, yprev, 128, W1x, W1x, act, tid, w, jl, rg);

        if (doL0) {
            red_store(A, red4, w, l);
            __syncthreads();
            float v = fin_cell(red4, cell, bE0, c0);
            y0[(size_t)slot * BH + fidx] = v;
        }
        if (doL1) {
            const float* h1p = (slot == 1) ? zerobuf : ((slot & 1) ? h1A : h1B);
            phase512<false>(B, B, h1p, 128, W1h, W1h, act, tid, w, jl, rg);
            red_store(B, red4, w, l);
            __syncthreads();
            float v = fin_cell(red4, cell, bE1, c1);
            float* h1o = (slot & 1) ? h1B : h1A;
            h1o[fidx] = v;
        }

        if (slot < TT) {
            gen++;
            grid_barrier(gen);
        }
    }
    c0out[fidx] = c0;
    c1out[fidx] = c1;
    // final h1 at slot TT (even) -> h1A
}

// ---------------- persistent decoder ----------------
__global__ void __launch_bounds__(NTHR, 1) dec_kernel(
    const float* __restrict__ in_seq,
    const float4* __restrict__ pWd0x, const float4* __restrict__ pWd0c,
    const float4* __restrict__ pWdh0, const float4* __restrict__ pWdx1,
    const float4* __restrict__ pWdh1,
    const float4* __restrict__ pbD0, const float4* __restrict__ pbD0c,
    const float4* __restrict__ pbD1,
    const float* __restrict__ h0init, const float* __restrict__ h1init,
    const float* __restrict__ c0in, const float* __restrict__ c1in,
    float* __restrict__ h0A, float* __restrict__ h0B, float* __restrict__ h1hist)
{
    extern __shared__ __align__(16) unsigned char smraw[];
    ulonglong2* Wc  = (ulonglong2*)smraw;
    ulonglong2* Wh0 = Wc  + 4 * WSS;
    ulonglong2* Wx1 = Wh0 + 4 * WSS;
    ulonglong2* Wh1 = Wx1 + 4 * WSS;
    ulonglong2* W0x = Wh1 + 4 * WSS;
    u64* act = (u64*)(W0x + 4 * WSS64);
    float4* red4 = (float4*)(act + 2 * ACT_U64);

    int tid = threadIdx.x;
    int w = tid >> 5, l = tid & 31, jl = l & 3, rg = l >> 2;
    int j0 = blockIdx.x * 4;
    int cell = tid;
    int fr = cell >> 2, fjl = cell & 3;
    int fidx = (fr << 9) + j0 + fjl;

    {
        const ulonglong2* gc  = (const ulonglong2*)pWd0c + (size_t)j0 * HH;
        const ulonglong2* gh0 = (const ulonglong2*)pWdh0 + (size_t)j0 * HH;
        const ulonglong2* gx1 = (const ulonglong2*)pWdx1 + (size_t)j0 * HH;
        const ulonglong2* gh1 = (const ulonglong2*)pWdh1 + (size_t)j0 * HH;
#pragma unroll 2
        for (int i = tid; i < 4 * HH; i += NTHR) {
            int jj = i >> 9, kk = i & 511;
            Wc[jj * WSS + kk]  = gc[i];
            Wh0[jj * WSS + kk] = gh0[i];
            Wx1[jj * WSS + kk] = gx1[i];
            Wh1[jj * WSS + kk] = gh1[i];
        }
        const ulonglong2* g0x = (const ulonglong2*)pWd0x + (size_t)j0 * FF;
        if (tid < 4 * FF) {
            int jj = tid >> 6, kk = tid & 63;
            W0x[jj * WSS64 + kk] = g0x[tid];
        }
    }
    float4 bd0  = pbD0[j0 + fjl];
    float4 bd0c = pbD0c[j0 + fjl];
    float4 bd1  = pbD1[j0 + fjl];
    float c0 = c0in[fidx], c1 = c1in[fidx];
    __syncthreads();

    unsigned gen = 0;
    const float* h0prev = h0init;
    const float* h1prev = h1init;

    for (int t = 0; t < FUT; t++) {
        // ---- cell d0 ----
        u64 A[32];
        zero_acc(A);
        if (t == 0) {
            phase64_s(A, in_seq + (size_t)(TT - 1) * FF, TT * FF / 4, W0x, act, tid, w, jl, rg);
        } else {
            phase512<false>(A, A, h1hist + (size_t)(t - 1) * BH, 128, Wc, Wc, act, tid, w, jl, rg);
        }
        phase512<false>(A, A, h0prev, 128, Wh0, Wh0, act, tid, w, jl, rg);
        red_store(A, red4, w, l);
        __syncthreads();
        {
            float4 bsel = (t == 0) ? bd0 : bd0c;
            float v = fin_cell(red4, cell, bsel, c0);
            float* h0out = (t & 1) ? h0B : h0A;
            h0out[fidx] = v;
            gen++; grid_barrier(gen);

            // ---- cell d1 ----
            u64 R[32];
            zero_acc(R);
            phase512<false>(R, R, h0out, 128, Wx1, Wx1, act, tid, w, jl, rg);
            phase512<false>(R, R, h1prev, 128, Wh1, Wh1, act, tid, w, jl, rg);
            red_store(R, red4, w, l);
            __syncthreads();
            float v1 = fin_cell(red4, cell, bd1, c1);
            float* h1o = h1hist + (size_t)t * BH;
            h1o[fidx] = v1;
            if (t < FUT - 1) { gen++; grid_barrier(gen); }
            h0prev = h0out;
            h1prev = h1o;
        }
    }
}

// ---------------- setup kernels (pair-packed weights, unchanged format) ----------------
__global__ void pack_all_kernel(
    const float* __restrict__ s0, const float* __restrict__ s1,
    const float* __restrict__ s2, const float* __restrict__ s3,
    const float* __restrict__ s4, const float* __restrict__ s5,
    const float* __restrict__ s6, const float* __restrict__ s7,
    float4* __restrict__ d0, float4* __restrict__ d1,
    float4* __restrict__ d2, float4* __restrict__ d3,
    float4* __restrict__ d4, float4* __restrict__ d5,
    float4* __restrict__ d6, float4* __restrict__ d7,
    const float* __restrict__ bi0, const float* __restrict__ bh0,
    const float* __restrict__ bi1, const float* __restrict__ bh1,
    const float* __restrict__ bi2, const float* __restrict__ bh2,
    const float* __restrict__ bi3, const float* __restrict__ bh3,
    float4* __restrict__ pb0, float4* __restrict__ pb1,
    float4* __restrict__ pb2, float4* __restrict__ pb3)
{
    int m = blockIdx.y;
    int idx = blockIdx.x * 256 + threadIdx.x;
    if (m < 8) {
        const float* S; float4* D; int Kin;
        switch (m) {
            case 0: S = s0; D = d0; Kin = FF; break;
            case 1: S = s1; D = d1; Kin = HH; break;
            case 2: S = s2; D = d2; Kin = HH; break;
            case 3: S = s3; D = d3; Kin = HH; break;
            case 4: S = s4; D = d4; Kin = FF; break;
            case 5: S = s5; D = d5; Kin = HH; break;
            case 6: S = s6; D = d6; Kin = HH; break;
            default: S = s7; D = d7; Kin = HH; break;
        }
        int K2 = Kin >> 1;
        if (idx >= HH * K2) return;
        int jj = idx / K2, k2 = idx - jj * K2;
        int k = k2 * 2;
        D[idx * 2 + 0] = make_float4(S[jj * Kin + k], S[jj * Kin + k + 1],
                                     S[(jj + 512) * Kin + k], S[(jj + 512) * Kin + k + 1]);
        D[idx * 2 + 1] = make_float4(S[(jj + 1024) * Kin + k], S[(jj + 1024) * Kin + k + 1],
                                     S[(jj + 1536) * Kin + k], S[(jj + 1536) * Kin + k + 1]);
    } else {
        if (idx >= 4 * HH) return;
        int which = idx >> 9, jj = idx & 511;
        const float* A; const float* Bb; float4* P;
        switch (which) {
            case 0: A = bi0; Bb = bh0; P = pb0; break;
            case 1: A = bi1; Bb = bh1; P = pb1; break;
            case 2: A = bi2; Bb = bh2; P = pb2; break;
            default: A = bi3; Bb = bh3; P = pb3; break;
        }
        P[jj] = make_float4(A[jj] + Bb[jj], A[jj + 512] + Bb[jj + 512],
                            A[jj + 1024] + Bb[jj + 1024], A[jj + 1536] + Bb[jj + 1536]);
    }
}

// W' = Wih0 @ fcW (pair-packed out), b' = b_d0 + Wih0 @ fc_b. Reads RAW inputs.
__global__ void combine_dec0_kernel(
    const float* __restrict__ dWih0, const float* __restrict__ fcW,
    const float* __restrict__ dbih0, const float* __restrict__ dbhh0,
    const float* __restrict__ fcb,
    float4* __restrict__ Pc, float4* __restrict__ pbc)
{
    int idx = blockIdx.x * 256 + threadIdx.x;       // HH * 256 entries (j, k2)
    if (idx >= HH * 256) return;
    int jj = idx >> 8, h = (idx & 255) * 2;
    float si0 = 0, si1 = 0, sf0 = 0, sf1 = 0, sg0 = 0, sg1 = 0, so0 = 0, so1 = 0;
#pragma unroll 4
    for (int n = 0; n < FF; n++) {
        float f0 = fcW[n * HH + h], f1 = fcW[n * HH + h + 1];
        float wi = dWih0[jj * FF + n];
        float wf = dWih0[(jj + 512) * FF + n];
        float wg = dWih0[(jj + 1024) * FF + n];
        float wo = dWih0[(jj + 1536) * FF + n];
        si0 += wi * f0; si1 += wi * f1;
        sf0 += wf * f0; sf1 += wf * f1;
        sg0 += wg * f0; sg1 += wg * f1;
        so0 += wo * f0; so1 += wo * f1;
    }
    Pc[idx * 2 + 0] = make_float4(si0, si1, sf0, sf1);
    Pc[idx * 2 + 1] = make_float4(sg0, sg1, so0, so1);
    if ((idx & 255) == 0) {
        float bi = dbih0[jj] + dbhh0[jj];
        float bf = dbih0[jj + 512] + dbhh0[jj + 512];
        float bg = dbih0[jj + 1024] + dbhh0[jj + 1024];
        float bo = dbih0[jj + 1536] + dbhh0[jj + 1536];
#pragma unroll 4
        for (int n = 0; n < FF; n++) {
            float f = fcb[n];
            bi += dWih0[jj * FF + n] * f;
            bf += dWih0[(jj + 512) * FF + n] * f;
            bg += dWih0[(jj + 1024) * FF + n] * f;
            bo += dWih0[(jj + 1536) * FF + n] * f;
        }
        pbc[jj] = make_float4(bi, bf, bg, bo);
    }
}

__global__ void init_kernel(float* zerobuf) {
    int i = blockIdx.x * 256 + threadIdx.x;
    if (i < BH) zerobuf[i] = 0.f;
    if (i < NBLK * 8) g_flag[i] = 0;
    if (i == 0) g_bgen = 0;
}
__global__ void reset_bar_kernel() {
    int i = threadIdx.x;
    if (i < NBLK * 8) g_flag[i] = 0;
    if (i == 0) g_bgen = 0;
}

__global__ void final_fc_kernel(const float* __restrict__ h1hist, const float* __restrict__ fcW,
                                const float* __restrict__ fcb, float* __restrict__ out) {
    int t = blockIdx.y;
    int lx = blockIdx.x * 256 + threadIdx.x;
    int b = lx >> 6, n = lx & 63;
    const float4* h4 = (const float4*)(h1hist + ((size_t)t * BB + b) * HH);
    const float4* w4 = (const float4*)(fcW + (size_t)n * HH);
    float acc = fcb[n];
#pragma unroll 8
    for (int k = 0; k < HH / 4; k++) {
        float4 a = h4[k], ww = w4[k];
        acc += a.x * ww.x + a.y * ww.y + a.z * ww.z + a.w * ww.w;
    }
    out[((size_t)b * FUT + t) * FF + n] = acc;
}

// ---------------- host ----------------
extern "C" void kernel_launch(void* const* d_in, const int* in_sizes, int n_in,
                              void* d_out, int out_size) {
    const float* in_seq = (const float*)d_in[0];
    const float* eWih0  = (const float*)d_in[1];
    const float* eWhh0  = (const float*)d_in[2];
    const float* ebih0  = (const float*)d_in[3];
    const float* ebhh0  = (const float*)d_in[4];
    const float* eWih1  = (const float*)d_in[5];
    const float* eWhh1  = (const float*)d_in[6];
    const float* ebih1  = (const float*)d_in[7];
    const float* ebhh1  = (const float*)d_in[8];
    const float* dWih0  = (const float*)d_in[9];
    const float* dWhh0  = (const float*)d_in[10];
    const float* dbih0  = (const float*)d_in[11];
    const float* dbhh0  = (const float*)d_in[12];
    const float* dWih1  = (const float*)d_in[13];
    const float* dWhh1  = (const float*)d_in[14];
    const float* dbih1  = (const float*)d_in[15];
    const float* dbhh1  = (const float*)d_in[16];
    const float* fcW    = (const float*)d_in[17];
    const float* fcb    = (const float*)d_in[18];
    float* out = (float*)d_out;

    static int s_attr_done = 0;
    if (!s_attr_done) {
        cudaFuncSetAttribute(enc_kernel, cudaFuncAttributeMaxDynamicSharedMemorySize, ENC_SMEM);
        cudaFuncSetAttribute(dec_kernel, cudaFuncAttributeMaxDynamicSharedMemorySize, DEC_SMEM);
        s_attr_done = 1;
    }

    float4 *pWeih0, *pWehh0, *pWeih1, *pWehh1, *pWdih0, *pWdhh0, *pWdih1, *pWdhh1, *pWd0c;
    float4 *pbE0, *pbE1, *pbD0, *pbD1, *pbD0c;
    float *y0, *h1hist, *zerobuf, *c0, *c1, *h1A, *h1B, *h0A, *h0B;
    cudaGetSymbolAddress((void**)&y0,      g_y0);
    cudaGetSymbolAddress((void**)&h1hist,  g_h1hist);
    cudaGetSymbolAddress((void**)&zerobuf, g_zero);
    cudaGetSymbolAddress((void**)&c0,      g_c0);
    cudaGetSymbolAddress((void**)&c1,      g_c1);
    cudaGetSymbolAddress((void**)&h1A,     g_h1A);
    cudaGetSymbolAddress((void**)&h1B,     g_h1B);
    cudaGetSymbolAddress((void**)&h0A,     g_h0A);
    cudaGetSymbolAddress((void**)&h0B,     g_h0B);
    cudaGetSymbolAddress((void**)&pWeih0,  g_pW_enc_ih0);
    cudaGetSymbolAddress((void**)&pWehh0,  g_pW_enc_hh0);
    cudaGetSymbolAddress((void**)&pWeih1,  g_pW_enc_ih1);
    cudaGetSymbolAddress((void**)&pWehh1,  g_pW_enc_hh1);
    cudaGetSymbolAddress((void**)&pWdih0,  g_pW_dec_ih0);
    cudaGetSymbolAddress((void**)&pWdhh0,  g_pW_dec_hh0);
    cudaGetSymbolAddress((void**)&pWdih1,  g_pW_dec_ih1);
    cudaGetSymbolAddress((void**)&pWdhh1,  g_pW_dec_hh1);
    cudaGetSymbolAddress((void**)&pWd0c,   g_pW_dec0c);
    cudaGetSymbolAddress((void**)&pbE0,    g_pb_enc0);
    cudaGetSymbolAddress((void**)&pbE1,    g_pb_enc1);
    cudaGetSymbolAddress((void**)&pbD0,    g_pb_dec0);
    cudaGetSymbolAddress((void**)&pbD1,    g_pb_dec1);
    cudaGetSymbolAddress((void**)&pbD0c,   g_pb_dec0c);

    // Launch order: 2 harness pre-launches + [pack, combine, init, enc] -> enc at idx 5.
    {
        dim3 grid(512, 9);
        pack_all_kernel<<<grid, 256>>>(
            eWih0, eWhh0, eWih1, eWhh1, dWih0, dWhh0, dWih1, dWhh1,
            pWeih0, pWehh0, pWeih1, pWehh1, pWdih0, pWdhh0, pWdih1, pWdhh1,
            ebih0, ebhh0, ebih1, ebhh1, dbih0, dbhh0, dbih1, dbhh1,
            pbE0, pbE1, pbD0, pbD1);
    }
    combine_dec0_kernel<<<(HH * 256 + 255) / 256, 256>>>(
        dWih0, fcW, dbih0, dbhh0, fcb, pWd0c, pbD0c);
    init_kernel<<<(BH + 255) / 256, 256>>>(zerobuf);

    enc_kernel<<<NBLK, NTHR, ENC_SMEM>>>(
        in_seq, pWeih0, pWehh0, pWeih1, pWehh1, pbE0, pbE1,
        zerobuf, y0, h1A, h1B, c0, c1);

    reset_bar_kernel<<<1, 1024>>>();

    dec_kernel<<<NBLK, NTHR, DEC_SMEM>>>(
        in_seq, pWdih0, pWd0c, pWdhh0, pWdih1, pWdhh1,
        pbD0, pbD0c, pbD1,
        y0 + (size_t)(TT - 1) * BH,
        h1A,
        c0, c1, h0A, h0B, h1hist);

    {
        dim3 grid(16, FUT);
        final_fc_kernel<<<grid, 256>>>(h1hist, fcW, fcb, out);
    }
}

// round 14
// speedup vs baseline: 1.0260x; 1.0260x over previous
#include <cuda_runtime.h>

// LSTM seq2seq: B=64, T=512, F=64, H=512, FUT=96 — persistent v8 (= v7, RGS=10).
// R13 trap root-cause: RGS=9 (odd u64 stride) broke 16-B alignment of the
// ulonglong2 act loads. v8 uses RGS=10: even stride (aligned LDS.128) AND
// conflict-free (start word 20*rg mod 32 -> 8 disjoint 4-word windows).

#define BB 64
#define TT 512
#define FF 64
#define HH 512
#define FUT 96
#define BH (BB*HH)          // 32768

#define NBLK 128
#define NTHR 256
#define WSS   514           // ulonglong2 per j row (K=512)
#define WSS64 66            // ulonglong2 per j row (K=64)
#define K2S 80              // u64 stride per k2 (8 row-groups x 10)
#define RGS 10              // u64 stride per row-group (even: keeps 16-B align)
#define ACT_U64 (32*K2S)    // one act buffer: 32 k2 x 80 u64 = 2560
#define RED_F4  2304        // reduction tile: 8 warps x 32 lanes x 9 float4

typedef unsigned long long u64;

// ---------------- device scratch ----------------
__device__ float  g_y0[TT*BB*HH];
__device__ float  g_h1hist[FUT*BB*HH];
__device__ float  g_zero[BH];
__device__ float  g_c0[BH], g_c1[BH];
__device__ float  g_h1A[BH], g_h1B[BH], g_h0A[BH], g_h0B[BH];

// pair-packed weights: per (j,k2): float4 {i(k),i(k+1),f(k),f(k+1)}, float4 {g..,o..}
__device__ float4 g_pW_enc_ih0[HH*FF];
__device__ float4 g_pW_enc_hh0[HH*HH];
__device__ float4 g_pW_enc_ih1[HH*HH];
__device__ float4 g_pW_enc_hh1[HH*HH];
__device__ float4 g_pW_dec_ih0[HH*FF];
__device__ float4 g_pW_dec_hh0[HH*HH];
__device__ float4 g_pW_dec_ih1[HH*HH];
__device__ float4 g_pW_dec_hh1[HH*HH];
__device__ float4 g_pW_dec0c[HH*HH];
__device__ float4 g_pb_enc0[HH], g_pb_enc1[HH], g_pb_dec0[HH], g_pb_dec1[HH], g_pb_dec0c[HH];

__device__ unsigned g_bgen;
__device__ unsigned g_flag[NBLK*8];

// ---------------- f32x2 helpers ----------------
__device__ __forceinline__ u64 pack2(float a, float b) {
    u64 r;
    asm("mov.b64 %0, {%1, %2};" : "=l"(r) : "r"(__float_as_uint(a)), "r"(__float_as_uint(b)));
    return r;
}
__device__ __forceinline__ float2 unpack2(u64 v) {
    unsigned int lo, hi;
    asm("mov.b64 {%0, %1}, %2;" : "=r"(lo), "=r"(hi) : "l"(v));
    return make_float2(__uint_as_float(lo), __uint_as_float(hi));
}
__device__ __forceinline__ void ffma2(u64& d, u64 a, u64 b) {
    asm("fma.rn.f32x2 %0, %1, %2, %0;" : "+l"(d) : "l"(a), "l"(b));
}

// ---------------- flag-tree grid barrier ----------------
__device__ __forceinline__ void grid_barrier(unsigned gen) {
    __syncthreads();
    int tid = threadIdx.x;
    if (blockIdx.x == 0) {
        if (tid > 0 && tid < NBLK) {
            unsigned v;
            do {
                asm volatile("ld.acquire.gpu.u32 %0, [%1];" : "=r"(v) : "l"(&g_flag[tid * 8]));
            } while (v < gen);
        }
        __syncthreads();
        if (tid == 0) {
            asm volatile("st.release.gpu.u32 [%0], %1;" :: "l"(&g_bgen), "r"(gen));
        }
    } else {
        if (tid == 0) {
            asm volatile("st.release.gpu.u32 [%0], %1;" :: "l"(&g_flag[blockIdx.x * 8]), "r"(gen));
            unsigned v;
            do {
                asm volatile("ld.acquire.gpu.u32 %0, [%1];" : "=r"(v) : "l"(&g_bgen));
            } while (v < gen);
        }
        __syncthreads();
    }
}

// ---------------- chunk compute: lane = (jl, rg), 8 rows per lane ----------------
// A[u*4+g]: row rg*8+u, gates g in {i,f,g,o}; each u64 = 2 k-lane partials.
// Warp w covers k2l = w + 8*kk, kk 0..3 within a 32-k2 chunk.
__device__ __forceinline__ void chunk_s(
    u64* __restrict__ A, const ulonglong2* __restrict__ Wt,
    const u64* __restrict__ ab, int w, int rg)
{
#pragma unroll
    for (int kk = 0; kk < 4; kk++) {
        int k2l = w + 8 * kk;
        const u64* ar = ab + k2l * K2S + rg * RGS;
        ulonglong2 a0 = *(const ulonglong2*)(ar);
        ulonglong2 a1 = *(const ulonglong2*)(ar + 2);
        ulonglong2 a2 = *(const ulonglong2*)(ar + 4);
        ulonglong2 a3 = *(const ulonglong2*)(ar + 6);
        ulonglong2 wif = Wt[k2l * 2], wgo = Wt[k2l * 2 + 1];
        u64 au[8] = {a0.x, a0.y, a1.x, a1.y, a2.x, a2.y, a3.x, a3.y};
#pragma unroll
        for (int u = 0; u < 8; u++) {
            ffma2(A[u * 4 + 0], au[u], wif.x);
            ffma2(A[u * 4 + 1], au[u], wif.y);
            ffma2(A[u * 4 + 2], au[u], wgo.x);
            ffma2(A[u * 4 + 3], au[u], wgo.y);
        }
    }
}

__device__ __forceinline__ void chunk_d(
    u64* __restrict__ A, u64* __restrict__ B,
    const ulonglong2* __restrict__ Wa, const ulonglong2* __restrict__ Wb,
    const u64* __restrict__ ab, int w, int rg)
{
#pragma unroll
    for (int kk = 0; kk < 4; kk++) {
        int k2l = w + 8 * kk;
        const u64* ar = ab + k2l * K2S + rg * RGS;
        ulonglong2 a0 = *(const ulonglong2*)(ar);
        ulonglong2 a1 = *(const ulonglong2*)(ar + 2);
        ulonglong2 a2 = *(const ulonglong2*)(ar + 4);
        ulonglong2 a3 = *(const ulonglong2*)(ar + 6);
        ulonglong2 waif = Wa[k2l * 2], wago = Wa[k2l * 2 + 1];
        ulonglong2 wbif = Wb[k2l * 2], wbgo = Wb[k2l * 2 + 1];
        u64 au[8] = {a0.x, a0.y, a1.x, a1.y, a2.x, a2.y, a3.x, a3.y};
#pragma unroll
        for (int u = 0; u < 8; u++) {
            ffma2(A[u * 4 + 0], au[u], waif.x);
            ffma2(A[u * 4 + 1], au[u], waif.y);
            ffma2(A[u * 4 + 2], au[u], wago.x);
            ffma2(A[u * 4 + 3], au[u], wago.y);
            ffma2(B[u * 4 + 0], au[u], wbif.x);
            ffma2(B[u * 4 + 1], au[u], wbif.y);
            ffma2(B[u * 4 + 2], au[u], wbgo.x);
            ffma2(B[u * 4 + 3], au[u], wbgo.y);
        }
    }
}

// ---------------- staged K=512 phase; x: [64][xs4 float4] row-major ----------------
template <bool DUAL>
__device__ __forceinline__ void phase512(
    u64* __restrict__ A, u64* __restrict__ B,
    const float* __restrict__ x, int xs4,
    const ulonglong2* __restrict__ Wa, const ulonglong2* __restrict__ Wb,
    u64* __restrict__ act, int tid, int w, int jl, int rg)
{
    const float4* x4 = (const float4*)x;
    int r = tid & 63, qg = tid >> 6;             // 256 thr: 4 stagers per row
    int rslot = (r >> 3) * RGS + (r & 7);        // staggered row offset
    const float4* xr = x4 + (size_t)r * xs4 + qg * 4;
    float4 pf[4];
#pragma unroll
    for (int u = 0; u < 4; u++) pf[u] = xr[u];
#pragma unroll 1
    for (int c = 0; c < 8; c++) {
        u64* buf = act + (c & 1) * ACT_U64;
#pragma unroll
        for (int u = 0; u < 4; u++) {
            int q = qg * 4 + u;
            buf[(2 * q) * K2S + rslot]     = pack2(pf[u].x, pf[u].y);
            buf[(2 * q + 1) * K2S + rslot] = pack2(pf[u].z, pf[u].w);
        }
        __syncthreads();
        if (c < 7) {
#pragma unroll
            for (int u = 0; u < 4; u++) pf[u] = xr[(c + 1) * 16 + u];
        }
        if (DUAL) chunk_d(A, B, Wa + jl * WSS + c * 64, Wb + jl * WSS + c * 64, buf, w, rg);
        else      chunk_s(A, Wa + jl * WSS + c * 64, buf, w, rg);
    }
}

// K=64 phase (input projection); uses act buffer 1 (parity-safe vs phase512 start).
__device__ __forceinline__ void phase64_s(
    u64* __restrict__ A, const float* __restrict__ x, int xs4,
    const ulonglong2* __restrict__ W, u64* __restrict__ act,
    int tid, int w, int jl, int rg)
{
    const float4* x4 = (const float4*)x;
    int r = tid & 63, qg = tid >> 6;
    int rslot = (r >> 3) * RGS + (r & 7);
    const float4* xr = x4 + (size_t)r * xs4 + qg * 4;
    u64* buf = act + ACT_U64;
#pragma unroll
    for (int u = 0; u < 4; u++) {
        float4 v = xr[u];
        int q = qg * 4 + u;
        buf[(2 * q) * K2S + rslot]     = pack2(v.x, v.y);
        buf[(2 * q + 1) * K2S + rslot] = pack2(v.z, v.w);
    }
    __syncthreads();
    chunk_s(A, W + jl * WSS64, buf, w, rg);
}

// ---------------- reduction: fold k-lanes, store float4 per (lane,row) ----------------
__device__ __forceinline__ void red_store(const u64* __restrict__ A,
                                          float4* __restrict__ red4, int w, int l)
{
    float4* p = red4 + (w * 32 + l) * 9;
#pragma unroll
    for (int u = 0; u < 8; u++) {
        float2 a = unpack2(A[u * 4 + 0]), b = unpack2(A[u * 4 + 1]);
        float2 cc = unpack2(A[u * 4 + 2]), d = unpack2(A[u * 4 + 3]);
        p[u] = make_float4(a.x + a.y, b.x + b.y, cc.x + cc.y, d.x + d.y);
    }
}

// Finalize one cell (after __syncthreads): sum 8 warp partials + bias, LSTM math.
__device__ __forceinline__ float fin_cell(const float4* __restrict__ red4,
                                          int cell, float4 bias, float& c)
{
    int r = cell >> 2, jl2 = cell & 3;
    int off = ((r >> 3) * 4 + jl2) * 9 + (r & 7);
    float4 s = bias;
#pragma unroll
    for (int w2 = 0; w2 < 8; w2++) {
        float4 v = red4[w2 * 288 + off];
        s.x += v.x; s.y += v.y; s.z += v.z; s.w += v.w;
    }
    float si = 1.f / (1.f + __expf(-s.x));
    float sf = 1.f / (1.f + __expf(-s.y));
    float so = 1.f / (1.f + __expf(-s.w));
    float cn = sf * c + si * tanhf(s.z);
    c = cn;
    return so * tanhf(cn);
}

__device__ __forceinline__ void zero_acc(u64* A) {
#pragma unroll
    for (int i = 0; i < 32; i++) A[i] = 0ULL;
}

#define ENC_SMEM ((3*4*WSS + 4*WSS64)*16 + 2*ACT_U64*8 + RED_F4*16)   // 180736
#define DEC_SMEM ((4*4*WSS + 4*WSS64)*16 + 2*ACT_U64*8 + RED_F4*16)   // 213632

// ---------------- persistent encoder: L0 + L1 software-pipelined ----------------
__global__ void __launch_bounds__(NTHR, 1) enc_kernel(
    const float* __restrict__ in_seq,
    const float4* __restrict__ pW0x, const float4* __restrict__ pW0h,
    const float4* __restrict__ pW1x, const float4* __restrict__ pW1h,
    const float4* __restrict__ pb0, const float4* __restrict__ pb1,
    const float* __restrict__ zerobuf,
    float* __restrict__ y0, float* __restrict__ h1A, float* __restrict__ h1B,
    float* __restrict__ c0out, float* __restrict__ c1out)
{
    extern __shared__ __align__(16) unsigned char smraw[];
    ulonglong2* W0h = (ulonglong2*)smraw;
    ulonglong2* W1x = W0h + 4 * WSS;
    ulonglong2* W1h = W1x + 4 * WSS;
    ulonglong2* W0x = W1h + 4 * WSS;
    u64* act = (u64*)(W0x + 4 * WSS64);
    float4* red4 = (float4*)(act + 2 * ACT_U64);

    int tid = threadIdx.x;
    int w = tid >> 5, l = tid & 31, jl = l & 3, rg = l >> 2;
    int j0 = blockIdx.x * 4;
    int cell = tid;
    int fr = cell >> 2, fjl = cell & 3;
    int fidx = (fr << 9) + j0 + fjl;

    {   // load smem weight tiles (once)
        const ulonglong2* g0h = (const ulonglong2*)pW0h + (size_t)j0 * HH;
        const ulonglong2* g1x = (const ulonglong2*)pW1x + (size_t)j0 * HH;
        const ulonglong2* g1h = (const ulonglong2*)pW1h + (size_t)j0 * HH;
#pragma unroll 2
        for (int i = tid; i < 4 * HH; i += NTHR) {
            int jj = i >> 9, kk = i & 511;
            W0h[jj * WSS + kk] = g0h[i];
            W1x[jj * WSS + kk] = g1x[i];
            W1h[jj * WSS + kk] = g1h[i];
        }
        const ulonglong2* g0x = (const ulonglong2*)pW0x + (size_t)j0 * FF;
        if (tid < 4 * FF) {
            int jj = tid >> 6, kk = tid & 63;
            W0x[jj * WSS64 + kk] = g0x[tid];
        }
    }
    float4 bE0 = pb0[j0 + fjl], bE1 = pb1[j0 + fjl];
    float c0 = 0.f, c1 = 0.f;
    __syncthreads();

    unsigned gen = 0;
    for (int slot = 0; slot <= TT; slot++) {
        bool doL0 = (slot < TT);
        bool doL1 = (slot > 0);
        const float* yprev = (slot == 0) ? zerobuf : (y0 + (size_t)(slot - 1) * BH);

        u64 A[32], B[32];
        if (doL0) {
            zero_acc(A);
            phase64_s(A, in_seq + (size_t)slot * FF, TT * FF / 4, W0x, act, tid, w, jl, rg);
        }
        if (doL1) zero_acc(B);

        if (doL0 && doL1)
            phase512<true>(A, B, yprev, 128, W0h, W1x, act, tid, w, jl, rg);
        else if (doL0)
            phase512<false>(A, A, yprev, 128, W0h, W0h, act, tid, w, jl, rg);
        else
            phase512<false>(B, B, yprev, 128, W1x, W1x, act, tid, w, jl, rg);

        if (doL0) {
            red_store(A, red4, w, l);
            __syncthreads();
            float v = fin_cell(red4, cell, bE0, c0);
            y0[(size_t)slot * BH + fidx] = v;
        }
        if (doL1) {
            const float* h1p = (slot == 1) ? zerobuf : ((slot & 1) ? h1A : h1B);
            phase512<false>(B, B, h1p, 128, W1h, W1h, act, tid, w, jl, rg);
            red_store(B, red4, w, l);
            __syncthreads();
            float v = fin_cell(red4, cell, bE1, c1);
            float* h1o = (slot & 1) ? h1B : h1A;
            h1o[fidx] = v;
        }

        if (slot < TT) {
            gen++;
            grid_barrier(gen);
        }
    }
    c0out[fidx] = c0;
    c1out[fidx] = c1;
    // final h1 at slot TT (even) -> h1A
}

// ---------------- persistent decoder ----------------
__global__ void __launch_bounds__(NTHR, 1) dec_kernel(
    const float* __restrict__ in_seq,
    const float4* __restrict__ pWd0x, const float4* __restrict__ pWd0c,
    const float4* __restrict__ pWdh0, const float4* __restrict__ pWdx1,
    const float4* __restrict__ pWdh1,
    const float4* __restrict__ pbD0, const float4* __restrict__ pbD0c,
    const float4* __restrict__ pbD1,
    const float* __restrict__ h0init, const float* __restrict__ h1init,
    const float* __restrict__ c0in, const float* __restrict__ c1in,
    float* __restrict__ h0A, float* __restrict__ h0B, float* __restrict__ h1hist)
{
    extern __shared__ __align__(16) unsigned char smraw[];
    ulonglong2* Wc  = (ulonglong2*)smraw;
    ulonglong2* Wh0 = Wc  + 4 * WSS;
    ulonglong2* Wx1 = Wh0 + 4 * WSS;
    ulonglong2* Wh1 = Wx1 + 4 * WSS;
    ulonglong2* W0x = Wh1 + 4 * WSS;
    u64* act = (u64*)(W0x + 4 * WSS64);
    float4* red4 = (float4*)(act + 2 * ACT_U64);

    int tid = threadIdx.x;
    int w = tid >> 5, l = tid & 31, jl = l & 3, rg = l >> 2;
    int j0 = blockIdx.x * 4;
    int cell = tid;
    int fr = cell >> 2, fjl = cell & 3;
    int fidx = (fr << 9) + j0 + fjl;

    {
        const ulonglong2* gc  = (const ulonglong2*)pWd0c + (size_t)j0 * HH;
        const ulonglong2* gh0 = (const ulonglong2*)pWdh0 + (size_t)j0 * HH;
        const ulonglong2* gx1 = (const ulonglong2*)pWdx1 + (size_t)j0 * HH;
        const ulonglong2* gh1 = (const ulonglong2*)pWdh1 + (size_t)j0 * HH;
#pragma unroll 2
        for (int i = tid; i < 4 * HH; i += NTHR) {
            int jj = i >> 9, kk = i & 511;
            Wc[jj * WSS + kk]  = gc[i];
            Wh0[jj * WSS + kk] = gh0[i];
            Wx1[jj * WSS + kk] = gx1[i];
            Wh1[jj * WSS + kk] = gh1[i];
        }
        const ulonglong2* g0x = (const ulonglong2*)pWd0x + (size_t)j0 * FF;
        if (tid < 4 * FF) {
            int jj = tid >> 6, kk = tid & 63;
            W0x[jj * WSS64 + kk] = g0x[tid];
        }
    }
    float4 bd0  = pbD0[j0 + fjl];
    float4 bd0c = pbD0c[j0 + fjl];
    float4 bd1  = pbD1[j0 + fjl];
    float c0 = c0in[fidx], c1 = c1in[fidx];
    __syncthreads();

    unsigned gen = 0;
    const float* h0prev = h0init;
    const float* h1prev = h1init;

    for (int t = 0; t < FUT; t++) {
        // ---- cell d0 ----
        u64 A[32];
        zero_acc(A);
        if (t == 0) {
            phase64_s(A, in_seq + (size_t)(TT - 1) * FF, TT * FF / 4, W0x, act, tid, w, jl, rg);
        } else {
            phase512<false>(A, A, h1hist + (size_t)(t - 1) * BH, 128, Wc, Wc, act, tid, w, jl, rg);
        }
        phase512<false>(A, A, h0prev, 128, Wh0, Wh0, act, tid, w, jl, rg);
        red_store(A, red4, w, l);
        __syncthreads();
        {
            float4 bsel = (t == 0) ? bd0 : bd0c;
            float v = fin_cell(red4, cell, bsel, c0);
            float* h0out = (t & 1) ? h0B : h0A;
            h0out[fidx] = v;
            gen++; grid_barrier(gen);

            // ---- cell d1 ----
            u64 R[32];
            zero_acc(R);
            phase512<false>(R, R, h0out, 128, Wx1, Wx1, act, tid, w, jl, rg);
            phase512<false>(R, R, h1prev, 128, Wh1, Wh1, act, tid, w, jl, rg);
            red_store(R, red4, w, l);
            __syncthreads();
            float v1 = fin_cell(red4, cell, bd1, c1);
            float* h1o = h1hist + (size_t)t * BH;
            h1o[fidx] = v1;
            if (t < FUT - 1) { gen++; grid_barrier(gen); }
            h0prev = h0out;
            h1prev = h1o;
        }
    }
}

// ---------------- setup kernels (pair-packed weights, unchanged format) ----------------
__global__ void pack_all_kernel(
    const float* __restrict__ s0, const float* __restrict__ s1,
    const float* __restrict__ s2, const float* __restrict__ s3,
    const float* __restrict__ s4, const float* __restrict__ s5,
    const float* __restrict__ s6, const float* __restrict__ s7,
    float4* __restrict__ d0, float4* __restrict__ d1,
    float4* __restrict__ d2, float4* __restrict__ d3,
    float4* __restrict__ d4, float4* __restrict__ d5,
    float4* __restrict__ d6, float4* __restrict__ d7,
    const float* __restrict__ bi0, const float* __restrict__ bh0,
    const float* __restrict__ bi1, const float* __restrict__ bh1,
    const float* __restrict__ bi2, const float* __restrict__ bh2,
    const float* __restrict__ bi3, const float* __restrict__ bh3,
    float4* __restrict__ pb0, float4* __restrict__ pb1,
    float4* __restrict__ pb2, float4* __restrict__ pb3)
{
    int m = blockIdx.y;
    int idx = blockIdx.x * 256 + threadIdx.x;
    if (m < 8) {
        const float* S; float4* D; int Kin;
        switch (m) {
            case 0: S = s0; D = d0; Kin = FF; break;
            case 1: S = s1; D = d1; Kin = HH; break;
            case 2: S = s2; D = d2; Kin = HH; break;
            case 3: S = s3; D = d3; Kin = HH; break;
            case 4: S = s4; D = d4; Kin = FF; break;
            case 5: S = s5; D = d5; Kin = HH; break;
            case 6: S = s6; D = d6; Kin = HH; break;
            default: S = s7; D = d7; Kin = HH; break;
        }
        int K2 = Kin >> 1;
        if (idx >= HH * K2) return;
        int jj = idx / K2, k2 = idx - jj * K2;
        int k = k2 * 2;
        D[idx * 2 + 0] = make_float4(S[jj * Kin + k], S[jj * Kin + k + 1],
                                     S[(jj + 512) * Kin + k], S[(jj + 512) * Kin + k + 1]);
        D[idx * 2 + 1] = make_float4(S[(jj + 1024) * Kin + k], S[(jj + 1024) * Kin + k + 1],
                                     S[(jj + 1536) * Kin + k], S[(jj + 1536) * Kin + k + 1]);
    } else {
        if (idx >= 4 * HH) return;
        int which = idx >> 9, jj = idx & 511;
        const float* A; const float* Bb; float4* P;
        switch (which) {
            case 0: A = bi0; Bb = bh0; P = pb0; break;
            case 1: A = bi1; Bb = bh1; P = pb1; break;
            case 2: A = bi2; Bb = bh2; P = pb2; break;
            default: A = bi3; Bb = bh3; P = pb3; break;
        }
        P[jj] = make_float4(A[jj] + Bb[jj], A[jj + 512] + Bb[jj + 512],
                            A[jj + 1024] + Bb[jj + 1024], A[jj + 1536] + Bb[jj + 1536]);
    }
}

// W' = Wih0 @ fcW (pair-packed out), b' = b_d0 + Wih0 @ fc_b. Reads RAW inputs.
__global__ void combine_dec0_kernel(
    const float* __restrict__ dWih0, const float* __restrict__ fcW,
    const float* __restrict__ dbih0, const float* __restrict__ dbhh0,
    const float* __restrict__ fcb,
    float4* __restrict__ Pc, float4* __restrict__ pbc)
{
    int idx = blockIdx.x * 256 + threadIdx.x;       // HH * 256 entries (j, k2)
    if (idx >= HH * 256) return;
    int jj = idx >> 8, h = (idx & 255) * 2;
    float si0 = 0, si1 = 0, sf0 = 0, sf1 = 0, sg0 = 0, sg1 = 0, so0 = 0, so1 = 0;
#pragma unroll 4
    for (int n = 0; n < FF; n++) {
        float f0 = fcW[n * HH + h], f1 = fcW[n * HH + h + 1];
        float wi = dWih0[jj * FF + n];
        float wf = dWih0[(jj + 512) * FF + n];
        float wg = dWih0[(jj + 1024) * FF + n];
        float wo = dWih0[(jj + 1536) * FF + n];
        si0 += wi * f0; si1 += wi * f1;
        sf0 += wf * f0; sf1 += wf * f1;
        sg0 += wg * f0; sg1 += wg * f1;
        so0 += wo * f0; so1 += wo * f1;
    }
    Pc[idx * 2 + 0] = make_float4(si0, si1, sf0, sf1);
    Pc[idx * 2 + 1] = make_float4(sg0, sg1, so0, so1);
    if ((idx & 255) == 0) {
        float bi = dbih0[jj] + dbhh0[jj];
        float bf = dbih0[jj + 512] + dbhh0[jj + 512];
        float bg = dbih0[jj + 1024] + dbhh0[jj + 1024];
        float bo = dbih0[jj + 1536] + dbhh0[jj + 1536];
#pragma unroll 4
        for (int n = 0; n < FF; n++) {
            float f = fcb[n];
            bi += dWih0[jj * FF + n] * f;
            bf += dWih0[(jj + 512) * FF + n] * f;
            bg += dWih0[(jj + 1024) * FF + n] * f;
            bo += dWih0[(jj + 1536) * FF + n] * f;
        }
        pbc[jj] = make_float4(bi, bf, bg, bo);
    }
}

__global__ void init_kernel(float* zerobuf) {
    int i = blockIdx.x * 256 + threadIdx.x;
    if (i < BH) zerobuf[i] = 0.f;
    if (i < NBLK * 8) g_flag[i] = 0;
    if (i == 0) g_bgen = 0;
}
__global__ void reset_bar_kernel() {
    int i = threadIdx.x;
    if (i < NBLK * 8) g_flag[i] = 0;
    if (i == 0) g_bgen = 0;
}

__global__ void final_fc_kernel(const float* __restrict__ h1hist, const float* __restrict__ fcW,
                                const float* __restrict__ fcb, float* __restrict__ out) {
    int t = blockIdx.y;
    int lx = blockIdx.x * 256 + threadIdx.x;
    int b = lx >> 6, n = lx & 63;
    const float4* h4 = (const float4*)(h1hist + ((size_t)t * BB + b) * HH);
    const float4* w4 = (const float4*)(fcW + (size_t)n * HH);
    float acc = fcb[n];
#pragma unroll 8
    for (int k = 0; k < HH / 4; k++) {
        float4 a = h4[k], ww = w4[k];
        acc += a.x * ww.x + a.y * ww.y + a.z * ww.z + a.w * ww.w;
    }
    out[((size_t)b * FUT + t) * FF + n] = acc;
}

// ---------------- host ----------------
extern "C" void kernel_launch(void* const* d_in, const int* in_sizes, int n_in,
                              void* d_out, int out_size) {
    const float* in_seq = (const float*)d_in[0];
    const float* eWih0  = (const float*)d_in[1];
    const float* eWhh0  = (const float*)d_in[2];
    const float* ebih0  = (const float*)d_in[3];
    const float* ebhh0  = (const float*)d_in[4];
    const float* eWih1  = (const float*)d_in[5];
    const float* eWhh1  = (const float*)d_in[6];
    const float* ebih1  = (const float*)d_in[7];
    const float* ebhh1  = (const float*)d_in[8];
    const float* dWih0  = (const float*)d_in[9];
    const float* dWhh0  = (const float*)d_in[10];
    const float* dbih0  = (const float*)d_in[11];
    const float* dbhh0  = (const float*)d_in[12];
    const float* dWih1  = (const float*)d_in[13];
    const float* dWhh1  = (const float*)d_in[14];
    const float* dbih1  = (const float*)d_in[15];
    const float* dbhh1  = (const float*)d_in[16];
    const float* fcW    = (const float*)d_in[17];
    const float* fcb    = (const float*)d_in[18];
    float* out = (float*)d_out;

    static int s_attr_done = 0;
    if (!s_attr_done) {
        cudaFuncSetAttribute(enc_kernel, cudaFuncAttributeMaxDynamicSharedMemorySize, ENC_SMEM);
        cudaFuncSetAttribute(dec_kernel, cudaFuncAttributeMaxDynamicSharedMemorySize, DEC_SMEM);
        s_attr_done = 1;
    }

    float4 *pWeih0, *pWehh0, *pWeih1, *pWehh1, *pWdih0, *pWdhh0, *pWdih1, *pWdhh1, *pWd0c;
    float4 *pbE0, *pbE1, *pbD0, *pbD1, *pbD0c;
    float *y0, *h1hist, *zerobuf, *c0, *c1, *h1A, *h1B, *h0A, *h0B;
    cudaGetSymbolAddress((void**)&y0,      g_y0);
    cudaGetSymbolAddress((void**)&h1hist,  g_h1hist);
    cudaGetSymbolAddress((void**)&zerobuf, g_zero);
    cudaGetSymbolAddress((void**)&c0,      g_c0);
    cudaGetSymbolAddress((void**)&c1,      g_c1);
    cudaGetSymbolAddress((void**)&h1A,     g_h1A);
    cudaGetSymbolAddress((void**)&h1B,     g_h1B);
    cudaGetSymbolAddress((void**)&h0A,     g_h0A);
    cudaGetSymbolAddress((void**)&h0B,     g_h0B);
    cudaGetSymbolAddress((void**)&pWeih0,  g_pW_enc_ih0);
    cudaGetSymbolAddress((void**)&pWehh0,  g_pW_enc_hh0);
    cudaGetSymbolAddress((void**)&pWeih1,  g_pW_enc_ih1);
    cudaGetSymbolAddress((void**)&pWehh1,  g_pW_enc_hh1);
    cudaGetSymbolAddress((void**)&pWdih0,  g_pW_dec_ih0);
    cudaGetSymbolAddress((void**)&pWdhh0,  g_pW_dec_hh0);
    cudaGetSymbolAddress((void**)&pWdih1,  g_pW_dec_ih1);
    cudaGetSymbolAddress((void**)&pWdhh1,  g_pW_dec_hh1);
    cudaGetSymbolAddress((void**)&pWd0c,   g_pW_dec0c);
    cudaGetSymbolAddress((void**)&pbE0,    g_pb_enc0);
    cudaGetSymbolAddress((void**)&pbE1,    g_pb_enc1);
    cudaGetSymbolAddress((void**)&pbD0,    g_pb_dec0);
    cudaGetSymbolAddress((void**)&pbD1,    g_pb_dec1);
    cudaGetSymbolAddress((void**)&pbD0c,   g_pb_dec0c);

    // Launch order: 2 harness pre-launches + [pack, combine, init, enc] -> enc at idx 5.
    {
        dim3 grid(512, 9);
        pack_all_kernel<<<grid, 256>>>(
            eWih0, eWhh0, eWih1, eWhh1, dWih0, dWhh0, dWih1, dWhh1,
            pWeih0, pWehh0, pWeih1, pWehh1, pWdih0, pWdhh0, pWdih1, pWdhh1,
            ebih0, ebhh0, ebih1, ebhh1, dbih0, dbhh0, dbih1, dbhh1,
            pbE0, pbE1, pbD0, pbD1);
    }
    combine_dec0_kernel<<<(HH * 256 + 255) / 256, 256>>>(
        dWih0, fcW, dbih0, dbhh0, fcb, pWd0c, pbD0c);
    init_kernel<<<(BH + 255) / 256, 256>>>(zerobuf);

    enc_kernel<<<NBLK, NTHR, ENC_SMEM>>>(
        in_seq, pWeih0, pWehh0, pWeih1, pWehh1, pbE0, pbE1,
        zerobuf, y0, h1A, h1B, c0, c1);

    reset_bar_kernel<<<1, 1024>>>();

    dec_kernel<<<NBLK, NTHR, DEC_SMEM>>>(
        in_seq, pWdih0, pWd0c, pWdhh0, pWdih1, pWdhh1,
        pbD0, pbD0c, pbD1,
        y0 + (size_t)(TT - 1) * BH,
        h1A,
        c0, c1, h0A, h0B, h1hist);

    {
        dim3 grid(16, FUT);
        final_fc_kernel<<<grid, 256>>>(h1hist, fcW, fcb, out);
    }
}